// round 12
// baseline (speedup 1.0000x reference)
#include <cuda_runtime.h>
#include <mma.h>
using namespace nvcuda;

#define DIM   1024
#define TOK   71
#define BATCH 1024
#define BT    (BATCH * TOK)   /* 72704 = 568*128 */
#define LAYERS 12

__device__ float g_x  [(size_t)BT * DIM];
__device__ float g_y  [3 * (size_t)BT * DIM];
__device__ float g_att[(size_t)BATCH * TOK * 72];
__device__ float g_h  [(size_t)BT * 2 * DIM];
__device__ float g_h2 [(size_t)BT * DIM];

__device__ __forceinline__ float blockSum256(float v, float* buf) {
    #pragma unroll
    for (int o = 16; o > 0; o >>= 1) v += __shfl_xor_sync(0xffffffffu, v, o);
    int lane = threadIdx.x & 31, w = threadIdx.x >> 5;
    if (lane == 0) buf[w] = v;
    __syncthreads();
    if (threadIdx.x == 0) { float s = 0.f;
        #pragma unroll
        for (int i = 0; i < 8; i++) s += buf[i];
        buf[0] = s; }
    __syncthreads();
    float r = buf[0];
    __syncthreads();
    return r;
}

// ---- embedding + LN ----
__global__ __launch_bounds__(256) void embed_ln_kernel(
    const int* __restrict__ fen, const int* __restrict__ mv,
    const float* __restrict__ rank_emb, const float* __restrict__ file_emb,
    const float* __restrict__ fen_emb,  const float* __restrict__ move_emb,
    const float* __restrict__ g, const float* __restrict__ bb,
    float* __restrict__ X)
{
    __shared__ float buf[8];
    int row = blockIdx.x, b = row / TOK, t = row % TOK, d0 = threadIdx.x * 4;
    float e[4];
    if (t < 64) {
        int i1 = fen[b * 133 + t], i2 = fen[b * 133 + 64 + t];
        float4 f1 = *(const float4*)(fen_emb  + (size_t)i1 * DIM + d0);
        float4 f2 = *(const float4*)(fen_emb  + (size_t)i2 * DIM + d0);
        float4 rr = *(const float4*)(rank_emb + (size_t)(t >> 3) * DIM + d0);
        float4 ff = *(const float4*)(file_emb + (size_t)(t & 7)  * DIM + d0);
        e[0] = 0.5f * (f1.x + f2.x + rr.x + ff.x);
        e[1] = 0.5f * (f1.y + f2.y + rr.y + ff.y);
        e[2] = 0.5f * (f1.z + f2.z + rr.z + ff.z);
        e[3] = 0.5f * (f1.w + f2.w + rr.w + ff.w);
    } else if (t < 69) {
        int i1 = fen[b * 133 + 64 + t];
        float4 f1 = *(const float4*)(fen_emb + (size_t)i1 * DIM + d0);
        e[0] = f1.x; e[1] = f1.y; e[2] = f1.z; e[3] = f1.w;
    } else {
        int j = t - 69, p = mv[b * 2 + j];
        float4 rr = *(const float4*)(rank_emb + (size_t)(p >> 3) * DIM + d0);
        float4 ff = *(const float4*)(file_emb + (size_t)(p & 7)  * DIM + d0);
        float4 mm = *(const float4*)(move_emb + (size_t)j * DIM + d0);
        e[0] = 0.58f * (rr.x + ff.x + mm.x);
        e[1] = 0.58f * (rr.y + ff.y + mm.y);
        e[2] = 0.58f * (rr.z + ff.z + mm.z);
        e[3] = 0.58f * (rr.w + ff.w + mm.w);
    }
    float s  = blockSum256(e[0] + e[1] + e[2] + e[3], buf);
    float sq = blockSum256(e[0]*e[0] + e[1]*e[1] + e[2]*e[2] + e[3]*e[3], buf);
    float m = s * (1.f / DIM);
    float rs = rsqrtf(fmaxf(sq * (1.f / DIM) - m * m, 0.f) + 1e-5f);
    float4 gg = *(const float4*)(g + d0), bv = *(const float4*)(bb + d0);
    float4 o;
    o.x = (e[0] - m) * rs * gg.x + bv.x;
    o.y = (e[1] - m) * rs * gg.y + bv.y;
    o.z = (e[2] - m) * rs * gg.z + bv.z;
    o.w = (e[3] - m) * rs * gg.w + bv.w;
    *(float4*)(X + (size_t)row * DIM + d0) = o;
}

// ---- in-place row LN ----
__global__ __launch_bounds__(256) void ln_rows_kernel(
    float* __restrict__ data, const float* __restrict__ g, const float* __restrict__ bb)
{
    __shared__ float buf[8];
    size_t base = (size_t)blockIdx.x * DIM;
    int d0 = threadIdx.x * 4;
    float4 v = *(float4*)(data + base + d0);
    float s  = blockSum256(v.x + v.y + v.z + v.w, buf);
    float sq = blockSum256(v.x*v.x + v.y*v.y + v.z*v.z + v.w*v.w, buf);
    float m = s * (1.f / DIM);
    float rs = rsqrtf(fmaxf(sq * (1.f / DIM) - m * m, 0.f) + 1e-5f);
    float4 gg = *(const float4*)(g + d0), bv = *(const float4*)(bb + d0);
    v.x = (v.x - m) * rs * gg.x + bv.x;
    v.y = (v.y - m) * rs * gg.y + bv.y;
    v.z = (v.z - m) * rs * gg.z + bv.z;
    v.w = (v.w - m) * rs * gg.w + bv.w;
    *(float4*)(data + base + d0) = v;
}

// ---- x = 0.7*(x + LN(y)) ----
__global__ __launch_bounds__(256) void ln_res_kernel(
    float* __restrict__ X, const float* __restrict__ Y,
    const float* __restrict__ g, const float* __restrict__ bb)
{
    __shared__ float buf[8];
    size_t base = (size_t)blockIdx.x * DIM;
    int d0 = threadIdx.x * 4;
    float4 y = *(const float4*)(Y + base + d0);
    float s  = blockSum256(y.x + y.y + y.z + y.w, buf);
    float sq = blockSum256(y.x*y.x + y.y*y.y + y.z*y.z + y.w*y.w, buf);
    float m = s * (1.f / DIM);
    float rs = rsqrtf(fmaxf(sq * (1.f / DIM) - m * m, 0.f) + 1e-5f);
    float4 gg = *(const float4*)(g + d0), bv = *(const float4*)(bb + d0);
    float4 x = *(float4*)(X + base + d0);
    x.x = 0.7f * (x.x + ((y.x - m) * rs * gg.x + bv.x));
    x.y = 0.7f * (x.y + ((y.y - m) * rs * gg.y + bv.y));
    x.z = 0.7f * (x.z + ((y.z - m) * rs * gg.z + bv.z));
    x.w = 0.7f * (x.w + ((y.w - m) * rs * gg.w + bv.w));
    *(float4*)(X + base + d0) = x;
}

// ============================================================================
// Pipelined tf32 wmma GEMM: C = A[M,K] @ B, fp32 accumulate.
//   TRANSB=false: B = W[K,N] row-major; TRANSB=true: B = W[N,K] (C = A @ W^T).
//   LEAKY: fused leaky_relu(0.2).
// 128x128x32 block tile, double-buffered smem (80KB dynamic), 8 warps (4x2),
// register prefetch of the next K-slab under the MMA work, 1 sync per slab.
// Requires M%128==0, N%128==0, K%32==0.
// ============================================================================
#define ABUF 5120   /* 128 rows * 40 ld */
template <bool TRANSB, bool LEAKY>
__global__ __launch_bounds__(256, 1) void gemm_tf32(
    const float* __restrict__ A, const float* __restrict__ W,
    float* __restrict__ C, int M, int N, int K)
{
    extern __shared__ float smem[];
    float* As = smem;              // 2 x ABUF
    float* Bs = smem + 2 * ABUF;   // 2 x ABUF (TRANSB: [128][40]; else [32][136])
    if (gridDim.z > 1) {
        W += (size_t)blockIdx.z * K * N;
        C += (size_t)blockIdx.z * M * N;
    }
    const int m0 = blockIdx.y * 128, n0 = blockIdx.x * 128;
    const int tid = threadIdx.x, warp = tid >> 5;
    const int wm = warp & 3, wn = warp >> 2;

    wmma::fragment<wmma::accumulator, 16, 16, 8, float> acc[2][4];
    #pragma unroll
    for (int i = 0; i < 2; i++)
        #pragma unroll
        for (int j = 0; j < 4; j++) wmma::fill_fragment(acc[i][j], 0.f);

    float4 ra[4], rb[4];

    auto loadTiles = [&](int k0) {
        #pragma unroll
        for (int q = 0; q < 4; q++) {
            int id = tid + q * 256;
            ra[q] = *(const float4*)(A + (size_t)(m0 + (id >> 3)) * K + k0 + (id & 7) * 4);
        }
        if constexpr (TRANSB) {
            #pragma unroll
            for (int q = 0; q < 4; q++) {
                int id = tid + q * 256;
                rb[q] = *(const float4*)(W + (size_t)(n0 + (id >> 3)) * K + k0 + (id & 7) * 4);
            }
        } else {
            #pragma unroll
            for (int q = 0; q < 4; q++) {
                int id = tid + q * 256;
                rb[q] = *(const float4*)(W + (size_t)(k0 + (id >> 5)) * N + n0 + (id & 31) * 4);
            }
        }
    };
    auto storeTiles = [&](float* ad, float* bd) {
        #pragma unroll
        for (int q = 0; q < 4; q++) {
            int id = tid + q * 256, r = id >> 3, c = (id & 7) * 4;
            ad[r * 40 + c + 0] = wmma::__float_to_tf32(ra[q].x);
            ad[r * 40 + c + 1] = wmma::__float_to_tf32(ra[q].y);
            ad[r * 40 + c + 2] = wmma::__float_to_tf32(ra[q].z);
            ad[r * 40 + c + 3] = wmma::__float_to_tf32(ra[q].w);
        }
        if constexpr (TRANSB) {
            #pragma unroll
            for (int q = 0; q < 4; q++) {
                int id = tid + q * 256, r = id >> 3, c = (id & 7) * 4;
                bd[r * 40 + c + 0] = wmma::__float_to_tf32(rb[q].x);
                bd[r * 40 + c + 1] = wmma::__float_to_tf32(rb[q].y);
                bd[r * 40 + c + 2] = wmma::__float_to_tf32(rb[q].z);
                bd[r * 40 + c + 3] = wmma::__float_to_tf32(rb[q].w);
            }
        } else {
            #pragma unroll
            for (int q = 0; q < 4; q++) {
                int id = tid + q * 256, r = id >> 5, c = (id & 31) * 4;
                bd[r * 136 + c + 0] = wmma::__float_to_tf32(rb[q].x);
                bd[r * 136 + c + 1] = wmma::__float_to_tf32(rb[q].y);
                bd[r * 136 + c + 2] = wmma::__float_to_tf32(rb[q].z);
                bd[r * 136 + c + 3] = wmma::__float_to_tf32(rb[q].w);
            }
        }
    };

    loadTiles(0);
    storeTiles(As, Bs);
    __syncthreads();

    const int KT = K >> 5;
    for (int kt = 0; kt < KT; kt++) {
        if (kt + 1 < KT) loadTiles((kt + 1) << 5);   // prefetch next slab into regs

        const float* Ac = As + (kt & 1) * ABUF;
        const float* Bc = Bs + (kt & 1) * ABUF;
        #pragma unroll
        for (int ks = 0; ks < 32; ks += 8) {
            wmma::fragment<wmma::matrix_a, 16, 16, 8, wmma::precision::tf32, wmma::row_major> af[2];
            wmma::load_matrix_sync(af[0], Ac + (wm * 32 + 0)  * 40 + ks, 40);
            wmma::load_matrix_sync(af[1], Ac + (wm * 32 + 16) * 40 + ks, 40);
            #pragma unroll
            for (int j = 0; j < 4; j++) {
                if constexpr (TRANSB) {
                    wmma::fragment<wmma::matrix_b, 16, 16, 8, wmma::precision::tf32, wmma::col_major> bf;
                    wmma::load_matrix_sync(bf, Bc + (wn * 64 + j * 16) * 40 + ks, 40);
                    wmma::mma_sync(acc[0][j], af[0], bf, acc[0][j]);
                    wmma::mma_sync(acc[1][j], af[1], bf, acc[1][j]);
                } else {
                    wmma::fragment<wmma::matrix_b, 16, 16, 8, wmma::precision::tf32, wmma::row_major> bf;
                    wmma::load_matrix_sync(bf, Bc + ks * 136 + wn * 64 + j * 16, 136);
                    wmma::mma_sync(acc[0][j], af[0], bf, acc[0][j]);
                    wmma::mma_sync(acc[1][j], af[1], bf, acc[1][j]);
                }
            }
        }
        if (kt + 1 < KT)
            storeTiles(As + ((kt + 1) & 1) * ABUF, Bs + ((kt + 1) & 1) * ABUF);
        __syncthreads();
    }

    #pragma unroll
    for (int i = 0; i < 2; i++)
        #pragma unroll
        for (int j = 0; j < 4; j++) {
            if constexpr (LEAKY) {
                #pragma unroll
                for (int t = 0; t < acc[i][j].num_elements; t++) {
                    float x = acc[i][j].x[t];
                    acc[i][j].x[t] = x > 0.f ? x : 0.2f * x;
                }
            }
            wmma::store_matrix_sync(
                C + (size_t)(m0 + wm * 32 + i * 16) * N + n0 + wn * 64 + j * 16,
                acc[i][j], N, wmma::mem_row_major);
        }
}
#define GEMM_SMEM (4 * ABUF * (int)sizeof(float))   /* 81920 bytes */

// ---- scores + softmax per batch item ----
__global__ __launch_bounds__(256) void scores_softmax_kernel(
    const float* __restrict__ Q, const float* __restrict__ Km, float* __restrict__ ATT)
{
    __shared__ float sm[5280];          // qs[80][33] | ks[80][33]; reused as S[71][72]
    float* qs = sm;
    float* ks = sm + 2640;
    const int b = blockIdx.x, tid = threadIdx.x;
    const int tx = tid & 15, ty = tid >> 4;

    float acc[5][5];
    #pragma unroll
    for (int i = 0; i < 5; i++)
        #pragma unroll
        for (int j = 0; j < 5; j++) acc[i][j] = 0.f;

    for (int kc = 0; kc < DIM; kc += 32) {
        __syncthreads();
        for (int idx = tid; idx < TOK * 32; idx += 256) {
            int r = idx >> 5, c = idx & 31;
            size_t gb = ((size_t)b * TOK + r) * DIM + kc + c;
            qs[r * 33 + c] = Q[gb];
            ks[r * 33 + c] = Km[gb];
        }
        __syncthreads();
        #pragma unroll 8
        for (int kk = 0; kk < 32; kk++) {
            float qv[5], kv[5];
            #pragma unroll
            for (int i = 0; i < 5; i++) qv[i] = (ty + 16 * i < TOK) ? qs[(ty + 16 * i) * 33 + kk] : 0.f;
            #pragma unroll
            for (int j = 0; j < 5; j++) kv[j] = (tx + 16 * j < TOK) ? ks[(tx + 16 * j) * 33 + kk] : 0.f;
            #pragma unroll
            for (int i = 0; i < 5; i++)
                #pragma unroll
                for (int j = 0; j < 5; j++) acc[i][j] += qv[i] * kv[j];
        }
    }
    __syncthreads();
    #pragma unroll
    for (int i = 0; i < 5; i++)
        #pragma unroll
        for (int j = 0; j < 5; j++) {
            int r = ty + 16 * i, c = tx + 16 * j;
            if (r < TOK && c < TOK) sm[r * 72 + c] = acc[i][j] * 0.03125f;
        }
    __syncthreads();

    const int lane = tid & 31, w = tid >> 5;
    for (int r = w; r < TOK; r += 8) {
        float v[3], p[3], mx = -1e30f;
        #pragma unroll
        for (int q = 0; q < 3; q++) {
            int c = lane + q * 32;
            v[q] = (c < TOK) ? sm[r * 72 + c] : -1e30f;
            mx = fmaxf(mx, v[q]);
        }
        #pragma unroll
        for (int o = 16; o > 0; o >>= 1) mx = fmaxf(mx, __shfl_xor_sync(0xffffffffu, mx, o));
        float sum = 0.f;
        #pragma unroll
        for (int q = 0; q < 3; q++) {
            int c = lane + q * 32;
            p[q] = (c < TOK) ? __expf(v[q] - mx) : 0.f;
            sum += p[q];
        }
        #pragma unroll
        for (int o = 16; o > 0; o >>= 1) sum += __shfl_xor_sync(0xffffffffu, sum, o);
        float inv = 1.f / sum;
        #pragma unroll
        for (int q = 0; q < 3; q++) {
            int c = lane + q * 32;
            if (c < TOK) ATT[(size_t)b * (TOK * 72) + r * 72 + c] = p[q] * inv;
        }
    }
}

// ---- AO = ATT @ V ----
__global__ __launch_bounds__(128) void av_kernel(
    const float* __restrict__ ATT, const float* __restrict__ V, float* __restrict__ AO)
{
    __shared__ float att_s[TOK * 72];
    const int b = blockIdx.y;
    const int d = blockIdx.x * 128 + threadIdx.x;
    for (int i = threadIdx.x; i < TOK * TOK; i += 128) {
        int t = i / TOK, s = i - t * TOK;
        att_s[t * 72 + s] = ATT[(size_t)b * (TOK * 72) + t * 72 + s];
    }
    __syncthreads();
    float acc[TOK];
    #pragma unroll
    for (int t = 0; t < TOK; t++) acc[t] = 0.f;
    for (int s = 0; s < TOK; s++) {
        float vv = V[((size_t)b * TOK + s) * DIM + d];
        #pragma unroll
        for (int t = 0; t < TOK; t++) acc[t] += att_s[t * 72 + s] * vv;
    }
    #pragma unroll
    for (int t = 0; t < TOK; t++)
        AO[((size_t)b * TOK + t) * DIM + d] = acc[t];
}

// ---- head ----
__global__ __launch_bounds__(256) void head_kernel(
    const float* __restrict__ X, const float* __restrict__ w,
    const float* __restrict__ bias, float* __restrict__ out)
{
    __shared__ float buf[8];
    const int b = blockIdx.x;
    float s = 0.f;
    for (int i = threadIdx.x; i < 2 * DIM; i += 256) {
        float xv = (i < DIM) ? X[((size_t)b * TOK + 69) * DIM + i]
                             : X[((size_t)b * TOK + 70) * DIM + i - DIM];
        s += xv * w[i];
    }
    s = blockSum256(s, buf);
    if (threadIdx.x == 0) out[b] = 1.f / (1.f + __expf(-(s + bias[0])));
}

extern "C" void kernel_launch(void* const* d_in, const int* in_sizes, int n_in,
                              void* d_out, int out_size)
{
    const int*   fen       = (const int*)  d_in[0];
    const int*   mv        = (const int*)  d_in[1];
    const float* rank_emb  = (const float*)d_in[2];
    const float* file_emb  = (const float*)d_in[3];
    const float* fen_emb   = (const float*)d_in[4];
    const float* move_emb  = (const float*)d_in[5];
    const float* ln_emb_g  = (const float*)d_in[6];
    const float* ln_emb_b  = (const float*)d_in[7];
    const float* qkv       = (const float*)d_in[8];
    const float* ln_q_g    = (const float*)d_in[9];
    const float* ln_q_b    = (const float*)d_in[10];
    const float* ln_k_g    = (const float*)d_in[11];
    const float* ln_k_b    = (const float*)d_in[12];
    const float* ln_attn_g = (const float*)d_in[13];
    const float* ln_attn_b = (const float*)d_in[14];
    const float* lin1_w    = (const float*)d_in[15];
    const float* lin2_w    = (const float*)d_in[16];
    const float* ln_ff_g   = (const float*)d_in[17];
    const float* ln_ff_b   = (const float*)d_in[18];
    const float* out_w     = (const float*)d_in[19];
    const float* out_b     = (const float*)d_in[20];
    float* out = (float*)d_out;

    float *X, *Y, *ATT, *H, *H2;
    cudaGetSymbolAddress((void**)&X,   g_x);
    cudaGetSymbolAddress((void**)&Y,   g_y);
    cudaGetSymbolAddress((void**)&ATT, g_att);
    cudaGetSymbolAddress((void**)&H,   g_h);
    cudaGetSymbolAddress((void**)&H2,  g_h2);

    cudaFuncSetAttribute(gemm_tf32<false, false>,
                         cudaFuncAttributeMaxDynamicSharedMemorySize, GEMM_SMEM);
    cudaFuncSetAttribute(gemm_tf32<true, true>,
                         cudaFuncAttributeMaxDynamicSharedMemorySize, GEMM_SMEM);

    embed_ln_kernel<<<BT, 256>>>(fen, mv, rank_emb, file_emb, fen_emb, move_emb,
                                 ln_emb_g, ln_emb_b, X);

    for (int l = 0; l < LAYERS; l++) {
        // QKV: Y[n] = X @ qkv[l][n], W row-major [D,D], 3 slabs via grid.z
        gemm_tf32<false, false><<<dim3(DIM / 128, BT / 128, 3), 256, GEMM_SMEM>>>(
            X, qkv + (size_t)l * 3 * DIM * DIM, Y, BT, DIM, DIM);

        ln_rows_kernel<<<BT, 256>>>(Y,                    ln_q_g + l * DIM, ln_q_b + l * DIM);
        ln_rows_kernel<<<BT, 256>>>(Y + (size_t)BT * DIM, ln_k_g + l * DIM, ln_k_b + l * DIM);

        scores_softmax_kernel<<<BATCH, 256>>>(Y, Y + (size_t)BT * DIM, ATT);
        av_kernel<<<dim3(DIM / 128, BATCH), 128>>>(ATT, Y + 2 * (size_t)BT * DIM, H2);

        ln_res_kernel<<<BT, 256>>>(X, H2, ln_attn_g + l * DIM, ln_attn_b + l * DIM);

        // FF: H = leaky(X @ lin1^T) [BT,2D]; H2 = leaky(H @ lin2^T) [BT,D]
        gemm_tf32<true, true><<<dim3(2 * DIM / 128, BT / 128, 1), 256, GEMM_SMEM>>>(
            X, lin1_w + (size_t)l * 2 * DIM * DIM, H, BT, 2 * DIM, DIM);
        gemm_tf32<true, true><<<dim3(DIM / 128, BT / 128, 1), 256, GEMM_SMEM>>>(
            H, lin2_w + (size_t)l * 2 * DIM * DIM, H2, BT, DIM, 2 * DIM);

        ln_res_kernel<<<BT, 256>>>(X, H2, ln_ff_g + l * DIM, ln_ff_b + l * DIM);
    }

    head_kernel<<<BATCH, 256>>>(X, out_w, out_b, out);
}

// round 13
// speedup vs baseline: 1.2294x; 1.2294x over previous
#include <cuda_runtime.h>
#include <mma.h>
using namespace nvcuda;

#define DIM   1024
#define TOK   71
#define BATCH 1024
#define BT    (BATCH * TOK)   /* 72704 = 568*128 */
#define LAYERS 12

__device__ float g_x  [(size_t)BT * DIM];
__device__ float g_y  [3 * (size_t)BT * DIM];
__device__ float g_att[(size_t)BATCH * TOK * 72];
__device__ float g_h  [(size_t)BT * 2 * DIM];
__device__ float g_h2 [(size_t)BT * DIM];

__device__ __forceinline__ float blockSum256(float v, float* buf) {
    #pragma unroll
    for (int o = 16; o > 0; o >>= 1) v += __shfl_xor_sync(0xffffffffu, v, o);
    int lane = threadIdx.x & 31, w = threadIdx.x >> 5;
    if (lane == 0) buf[w] = v;
    __syncthreads();
    if (threadIdx.x == 0) { float s = 0.f;
        #pragma unroll
        for (int i = 0; i < 8; i++) s += buf[i];
        buf[0] = s; }
    __syncthreads();
    float r = buf[0];
    __syncthreads();
    return r;
}

// ---- embedding + LN ----
__global__ __launch_bounds__(256) void embed_ln_kernel(
    const int* __restrict__ fen, const int* __restrict__ mv,
    const float* __restrict__ rank_emb, const float* __restrict__ file_emb,
    const float* __restrict__ fen_emb,  const float* __restrict__ move_emb,
    const float* __restrict__ g, const float* __restrict__ bb,
    float* __restrict__ X)
{
    __shared__ float buf[8];
    int row = blockIdx.x, b = row / TOK, t = row % TOK, d0 = threadIdx.x * 4;
    float e[4];
    if (t < 64) {
        int i1 = fen[b * 133 + t], i2 = fen[b * 133 + 64 + t];
        float4 f1 = *(const float4*)(fen_emb  + (size_t)i1 * DIM + d0);
        float4 f2 = *(const float4*)(fen_emb  + (size_t)i2 * DIM + d0);
        float4 rr = *(const float4*)(rank_emb + (size_t)(t >> 3) * DIM + d0);
        float4 ff = *(const float4*)(file_emb + (size_t)(t & 7)  * DIM + d0);
        e[0] = 0.5f * (f1.x + f2.x + rr.x + ff.x);
        e[1] = 0.5f * (f1.y + f2.y + rr.y + ff.y);
        e[2] = 0.5f * (f1.z + f2.z + rr.z + ff.z);
        e[3] = 0.5f * (f1.w + f2.w + rr.w + ff.w);
    } else if (t < 69) {
        int i1 = fen[b * 133 + 64 + t];
        float4 f1 = *(const float4*)(fen_emb + (size_t)i1 * DIM + d0);
        e[0] = f1.x; e[1] = f1.y; e[2] = f1.z; e[3] = f1.w;
    } else {
        int j = t - 69, p = mv[b * 2 + j];
        float4 rr = *(const float4*)(rank_emb + (size_t)(p >> 3) * DIM + d0);
        float4 ff = *(const float4*)(file_emb + (size_t)(p & 7)  * DIM + d0);
        float4 mm = *(const float4*)(move_emb + (size_t)j * DIM + d0);
        e[0] = 0.58f * (rr.x + ff.x + mm.x);
        e[1] = 0.58f * (rr.y + ff.y + mm.y);
        e[2] = 0.58f * (rr.z + ff.z + mm.z);
        e[3] = 0.58f * (rr.w + ff.w + mm.w);
    }
    float s  = blockSum256(e[0] + e[1] + e[2] + e[3], buf);
    float sq = blockSum256(e[0]*e[0] + e[1]*e[1] + e[2]*e[2] + e[3]*e[3], buf);
    float m = s * (1.f / DIM);
    float rs = rsqrtf(fmaxf(sq * (1.f / DIM) - m * m, 0.f) + 1e-5f);
    float4 gg = *(const float4*)(g + d0), bv = *(const float4*)(bb + d0);
    float4 o;
    o.x = (e[0] - m) * rs * gg.x + bv.x;
    o.y = (e[1] - m) * rs * gg.y + bv.y;
    o.z = (e[2] - m) * rs * gg.z + bv.z;
    o.w = (e[3] - m) * rs * gg.w + bv.w;
    *(float4*)(X + (size_t)row * DIM + d0) = o;
}

// ---- in-place row LN ----
__global__ __launch_bounds__(256) void ln_rows_kernel(
    float* __restrict__ data, const float* __restrict__ g, const float* __restrict__ bb)
{
    __shared__ float buf[8];
    size_t base = (size_t)blockIdx.x * DIM;
    int d0 = threadIdx.x * 4;
    float4 v = *(float4*)(data + base + d0);
    float s  = blockSum256(v.x + v.y + v.z + v.w, buf);
    float sq = blockSum256(v.x*v.x + v.y*v.y + v.z*v.z + v.w*v.w, buf);
    float m = s * (1.f / DIM);
    float rs = rsqrtf(fmaxf(sq * (1.f / DIM) - m * m, 0.f) + 1e-5f);
    float4 gg = *(const float4*)(g + d0), bv = *(const float4*)(bb + d0);
    v.x = (v.x - m) * rs * gg.x + bv.x;
    v.y = (v.y - m) * rs * gg.y + bv.y;
    v.z = (v.z - m) * rs * gg.z + bv.z;
    v.w = (v.w - m) * rs * gg.w + bv.w;
    *(float4*)(data + base + d0) = v;
}

// ---- x = 0.7*(x + LN(y)) ----
__global__ __launch_bounds__(256) void ln_res_kernel(
    float* __restrict__ X, const float* __restrict__ Y,
    const float* __restrict__ g, const float* __restrict__ bb)
{
    __shared__ float buf[8];
    size_t base = (size_t)blockIdx.x * DIM;
    int d0 = threadIdx.x * 4;
    float4 y = *(const float4*)(Y + base + d0);
    float s  = blockSum256(y.x + y.y + y.z + y.w, buf);
    float sq = blockSum256(y.x*y.x + y.y*y.y + y.z*y.z + y.w*y.w, buf);
    float m = s * (1.f / DIM);
    float rs = rsqrtf(fmaxf(sq * (1.f / DIM) - m * m, 0.f) + 1e-5f);
    float4 gg = *(const float4*)(g + d0), bv = *(const float4*)(bb + d0);
    float4 x = *(float4*)(X + base + d0);
    x.x = 0.7f * (x.x + ((y.x - m) * rs * gg.x + bv.x));
    x.y = 0.7f * (x.y + ((y.y - m) * rs * gg.y + bv.y));
    x.z = 0.7f * (x.z + ((y.z - m) * rs * gg.z + bv.z));
    x.w = 0.7f * (x.w + ((y.w - m) * rs * gg.w + bv.w));
    *(float4*)(X + base + d0) = x;
}

// ============================================================================
// Pipelined tf32 wmma GEMM, occupancy-preserving: C = A[M,K] @ B, fp32 acc.
//   TRANSB=false: B = W[K,N] row-major; TRANSB=true: B = W[N,K] (C = A @ W^T).
//   LEAKY: fused leaky_relu(0.2).
// 128x128x16 tile, double-buffered STATIC smem (<=48KB so 2 CTAs/SM),
// register prefetch of next slab under the MMAs, 1 sync per slab.
// ============================================================================
template <bool TRANSB, bool LEAKY>
__global__ __launch_bounds__(256, 2) void gemm_tf32(
    const float* __restrict__ A, const float* __restrict__ W,
    float* __restrict__ C, int M, int N, int K)
{
    constexpr int ASZ = 128 * 24;                    // 3072 floats / buffer
    constexpr int BSZ = TRANSB ? 128 * 24 : 16 * 136;
    __shared__ float As[2 * ASZ];
    __shared__ float Bs[2 * BSZ];

    if (gridDim.z > 1) {
        W += (size_t)blockIdx.z * K * N;
        C += (size_t)blockIdx.z * M * N;
    }
    const int m0 = blockIdx.y * 128, n0 = blockIdx.x * 128;
    const int tid = threadIdx.x, warp = tid >> 5;
    const int wm = warp & 3, wn = warp >> 2;

    wmma::fragment<wmma::accumulator, 16, 16, 8, float> acc[2][4];
    #pragma unroll
    for (int i = 0; i < 2; i++)
        #pragma unroll
        for (int j = 0; j < 4; j++) wmma::fill_fragment(acc[i][j], 0.f);

    float4 ra[2], rb[2];

    auto loadTiles = [&](int k0) {
        #pragma unroll
        for (int q = 0; q < 2; q++) {
            int id = tid + q * 256;
            ra[q] = *(const float4*)(A + (size_t)(m0 + (id >> 2)) * K + k0 + (id & 3) * 4);
        }
        if constexpr (TRANSB) {
            #pragma unroll
            for (int q = 0; q < 2; q++) {
                int id = tid + q * 256;
                rb[q] = *(const float4*)(W + (size_t)(n0 + (id >> 2)) * K + k0 + (id & 3) * 4);
            }
        } else {
            #pragma unroll
            for (int q = 0; q < 2; q++) {
                int id = tid + q * 256;
                rb[q] = *(const float4*)(W + (size_t)(k0 + (id >> 5)) * N + n0 + (id & 31) * 4);
            }
        }
    };
    auto storeTiles = [&](float* ad, float* bd) {
        #pragma unroll
        for (int q = 0; q < 2; q++) {
            int id = tid + q * 256, r = id >> 2, c = (id & 3) * 4;
            ad[r * 24 + c + 0] = wmma::__float_to_tf32(ra[q].x);
            ad[r * 24 + c + 1] = wmma::__float_to_tf32(ra[q].y);
            ad[r * 24 + c + 2] = wmma::__float_to_tf32(ra[q].z);
            ad[r * 24 + c + 3] = wmma::__float_to_tf32(ra[q].w);
        }
        if constexpr (TRANSB) {
            #pragma unroll
            for (int q = 0; q < 2; q++) {
                int id = tid + q * 256, r = id >> 2, c = (id & 3) * 4;
                bd[r * 24 + c + 0] = wmma::__float_to_tf32(rb[q].x);
                bd[r * 24 + c + 1] = wmma::__float_to_tf32(rb[q].y);
                bd[r * 24 + c + 2] = wmma::__float_to_tf32(rb[q].z);
                bd[r * 24 + c + 3] = wmma::__float_to_tf32(rb[q].w);
            }
        } else {
            #pragma unroll
            for (int q = 0; q < 2; q++) {
                int id = tid + q * 256, r = id >> 5, c = (id & 31) * 4;
                bd[r * 136 + c + 0] = wmma::__float_to_tf32(rb[q].x);
                bd[r * 136 + c + 1] = wmma::__float_to_tf32(rb[q].y);
                bd[r * 136 + c + 2] = wmma::__float_to_tf32(rb[q].z);
                bd[r * 136 + c + 3] = wmma::__float_to_tf32(rb[q].w);
            }
        }
    };

    loadTiles(0);
    storeTiles(As, Bs);
    __syncthreads();

    const int KT = K >> 4;
    for (int kt = 0; kt < KT; kt++) {
        if (kt + 1 < KT) loadTiles((kt + 1) << 4);   // prefetch next slab into regs

        const float* Ac = As + (kt & 1) * ASZ;
        const float* Bc = Bs + (kt & 1) * BSZ;
        #pragma unroll
        for (int ks = 0; ks < 16; ks += 8) {
            wmma::fragment<wmma::matrix_a, 16, 16, 8, wmma::precision::tf32, wmma::row_major> af[2];
            wmma::load_matrix_sync(af[0], Ac + (wm * 32 + 0)  * 24 + ks, 24);
            wmma::load_matrix_sync(af[1], Ac + (wm * 32 + 16) * 24 + ks, 24);
            #pragma unroll
            for (int j = 0; j < 4; j++) {
                if constexpr (TRANSB) {
                    wmma::fragment<wmma::matrix_b, 16, 16, 8, wmma::precision::tf32, wmma::col_major> bf;
                    wmma::load_matrix_sync(bf, Bc + (wn * 64 + j * 16) * 24 + ks, 24);
                    wmma::mma_sync(acc[0][j], af[0], bf, acc[0][j]);
                    wmma::mma_sync(acc[1][j], af[1], bf, acc[1][j]);
                } else {
                    wmma::fragment<wmma::matrix_b, 16, 16, 8, wmma::precision::tf32, wmma::row_major> bf;
                    wmma::load_matrix_sync(bf, Bc + ks * 136 + wn * 64 + j * 16, 136);
                    wmma::mma_sync(acc[0][j], af[0], bf, acc[0][j]);
                    wmma::mma_sync(acc[1][j], af[1], bf, acc[1][j]);
                }
            }
        }
        if (kt + 1 < KT)
            storeTiles(As + ((kt + 1) & 1) * ASZ, Bs + ((kt + 1) & 1) * BSZ);
        __syncthreads();
    }

    #pragma unroll
    for (int i = 0; i < 2; i++)
        #pragma unroll
        for (int j = 0; j < 4; j++) {
            if constexpr (LEAKY) {
                #pragma unroll
                for (int t = 0; t < acc[i][j].num_elements; t++) {
                    float x = acc[i][j].x[t];
                    acc[i][j].x[t] = x > 0.f ? x : 0.2f * x;
                }
            }
            wmma::store_matrix_sync(
                C + (size_t)(m0 + wm * 32 + i * 16) * N + n0 + wn * 64 + j * 16,
                acc[i][j], N, wmma::mem_row_major);
        }
}

// ---- scores + softmax per batch item ----
__global__ __launch_bounds__(256) void scores_softmax_kernel(
    const float* __restrict__ Q, const float* __restrict__ Km, float* __restrict__ ATT)
{
    __shared__ float sm[5280];          // qs[80][33] | ks[80][33]; reused as S[71][72]
    float* qs = sm;
    float* ks = sm + 2640;
    const int b = blockIdx.x, tid = threadIdx.x;
    const int tx = tid & 15, ty = tid >> 4;

    float acc[5][5];
    #pragma unroll
    for (int i = 0; i < 5; i++)
        #pragma unroll
        for (int j = 0; j < 5; j++) acc[i][j] = 0.f;

    for (int kc = 0; kc < DIM; kc += 32) {
        __syncthreads();
        for (int idx = tid; idx < TOK * 32; idx += 256) {
            int r = idx >> 5, c = idx & 31;
            size_t gb = ((size_t)b * TOK + r) * DIM + kc + c;
            qs[r * 33 + c] = Q[gb];
            ks[r * 33 + c] = Km[gb];
        }
        __syncthreads();
        #pragma unroll 8
        for (int kk = 0; kk < 32; kk++) {
            float qv[5], kv[5];
            #pragma unroll
            for (int i = 0; i < 5; i++) qv[i] = (ty + 16 * i < TOK) ? qs[(ty + 16 * i) * 33 + kk] : 0.f;
            #pragma unroll
            for (int j = 0; j < 5; j++) kv[j] = (tx + 16 * j < TOK) ? ks[(tx + 16 * j) * 33 + kk] : 0.f;
            #pragma unroll
            for (int i = 0; i < 5; i++)
                #pragma unroll
                for (int j = 0; j < 5; j++) acc[i][j] += qv[i] * kv[j];
        }
    }
    __syncthreads();
    #pragma unroll
    for (int i = 0; i < 5; i++)
        #pragma unroll
        for (int j = 0; j < 5; j++) {
            int r = ty + 16 * i, c = tx + 16 * j;
            if (r < TOK && c < TOK) sm[r * 72 + c] = acc[i][j] * 0.03125f;
        }
    __syncthreads();

    const int lane = tid & 31, w = tid >> 5;
    for (int r = w; r < TOK; r += 8) {
        float v[3], p[3], mx = -1e30f;
        #pragma unroll
        for (int q = 0; q < 3; q++) {
            int c = lane + q * 32;
            v[q] = (c < TOK) ? sm[r * 72 + c] : -1e30f;
            mx = fmaxf(mx, v[q]);
        }
        #pragma unroll
        for (int o = 16; o > 0; o >>= 1) mx = fmaxf(mx, __shfl_xor_sync(0xffffffffu, mx, o));
        float sum = 0.f;
        #pragma unroll
        for (int q = 0; q < 3; q++) {
            int c = lane + q * 32;
            p[q] = (c < TOK) ? __expf(v[q] - mx) : 0.f;
            sum += p[q];
        }
        #pragma unroll
        for (int o = 16; o > 0; o >>= 1) sum += __shfl_xor_sync(0xffffffffu, sum, o);
        float inv = 1.f / sum;
        #pragma unroll
        for (int q = 0; q < 3; q++) {
            int c = lane + q * 32;
            if (c < TOK) ATT[(size_t)b * (TOK * 72) + r * 72 + c] = p[q] * inv;
        }
    }
}

// ---- AO = ATT @ V ----
__global__ __launch_bounds__(128) void av_kernel(
    const float* __restrict__ ATT, const float* __restrict__ V, float* __restrict__ AO)
{
    __shared__ float att_s[TOK * 72];
    const int b = blockIdx.y;
    const int d = blockIdx.x * 128 + threadIdx.x;
    for (int i = threadIdx.x; i < TOK * TOK; i += 128) {
        int t = i / TOK, s = i - t * TOK;
        att_s[t * 72 + s] = ATT[(size_t)b * (TOK * 72) + t * 72 + s];
    }
    __syncthreads();
    float acc[TOK];
    #pragma unroll
    for (int t = 0; t < TOK; t++) acc[t] = 0.f;
    for (int s = 0; s < TOK; s++) {
        float vv = V[((size_t)b * TOK + s) * DIM + d];
        #pragma unroll
        for (int t = 0; t < TOK; t++) acc[t] += att_s[t * 72 + s] * vv;
    }
    #pragma unroll
    for (int t = 0; t < TOK; t++)
        AO[((size_t)b * TOK + t) * DIM + d] = acc[t];
}

// ---- head ----
__global__ __launch_bounds__(256) void head_kernel(
    const float* __restrict__ X, const float* __restrict__ w,
    const float* __restrict__ bias, float* __restrict__ out)
{
    __shared__ float buf[8];
    const int b = blockIdx.x;
    float s = 0.f;
    for (int i = threadIdx.x; i < 2 * DIM; i += 256) {
        float xv = (i < DIM) ? X[((size_t)b * TOK + 69) * DIM + i]
                             : X[((size_t)b * TOK + 70) * DIM + i - DIM];
        s += xv * w[i];
    }
    s = blockSum256(s, buf);
    if (threadIdx.x == 0) out[b] = 1.f / (1.f + __expf(-(s + bias[0])));
}

extern "C" void kernel_launch(void* const* d_in, const int* in_sizes, int n_in,
                              void* d_out, int out_size)
{
    const int*   fen       = (const int*)  d_in[0];
    const int*   mv        = (const int*)  d_in[1];
    const float* rank_emb  = (const float*)d_in[2];
    const float* file_emb  = (const float*)d_in[3];
    const float* fen_emb   = (const float*)d_in[4];
    const float* move_emb  = (const float*)d_in[5];
    const float* ln_emb_g  = (const float*)d_in[6];
    const float* ln_emb_b  = (const float*)d_in[7];
    const float* qkv       = (const float*)d_in[8];
    const float* ln_q_g    = (const float*)d_in[9];
    const float* ln_q_b    = (const float*)d_in[10];
    const float* ln_k_g    = (const float*)d_in[11];
    const float* ln_k_b    = (const float*)d_in[12];
    const float* ln_attn_g = (const float*)d_in[13];
    const float* ln_attn_b = (const float*)d_in[14];
    const float* lin1_w    = (const float*)d_in[15];
    const float* lin2_w    = (const float*)d_in[16];
    const float* ln_ff_g   = (const float*)d_in[17];
    const float* ln_ff_b   = (const float*)d_in[18];
    const float* out_w     = (const float*)d_in[19];
    const float* out_b     = (const float*)d_in[20];
    float* out = (float*)d_out;

    float *X, *Y, *ATT, *H, *H2;
    cudaGetSymbolAddress((void**)&X,   g_x);
    cudaGetSymbolAddress((void**)&Y,   g_y);
    cudaGetSymbolAddress((void**)&ATT, g_att);
    cudaGetSymbolAddress((void**)&H,   g_h);
    cudaGetSymbolAddress((void**)&H2,  g_h2);

    embed_ln_kernel<<<BT, 256>>>(fen, mv, rank_emb, file_emb, fen_emb, move_emb,
                                 ln_emb_g, ln_emb_b, X);

    for (int l = 0; l < LAYERS; l++) {
        // QKV: Y[n] = X @ qkv[l][n], W row-major [D,D], 3 slabs via grid.z
        gemm_tf32<false, false><<<dim3(DIM / 128, BT / 128, 3), 256>>>(
            X, qkv + (size_t)l * 3 * DIM * DIM, Y, BT, DIM, DIM);

        ln_rows_kernel<<<BT, 256>>>(Y,                    ln_q_g + l * DIM, ln_q_b + l * DIM);
        ln_rows_kernel<<<BT, 256>>>(Y + (size_t)BT * DIM, ln_k_g + l * DIM, ln_k_b + l * DIM);

        scores_softmax_kernel<<<BATCH, 256>>>(Y, Y + (size_t)BT * DIM, ATT);
        av_kernel<<<dim3(DIM / 128, BATCH), 128>>>(ATT, Y + 2 * (size_t)BT * DIM, H2);

        ln_res_kernel<<<BT, 256>>>(X, H2, ln_attn_g + l * DIM, ln_attn_b + l * DIM);

        // FF: H = leaky(X @ lin1^T) [BT,2D]; H2 = leaky(H @ lin2^T) [BT,D]
        gemm_tf32<true, true><<<dim3(2 * DIM / 128, BT / 128, 1), 256>>>(
            X, lin1_w + (size_t)l * 2 * DIM * DIM, H, BT, 2 * DIM, DIM);
        gemm_tf32<true, true><<<dim3(DIM / 128, BT / 128, 1), 256>>>(
            H, lin2_w + (size_t)l * 2 * DIM * DIM, H2, BT, DIM, 2 * DIM);

        ln_res_kernel<<<BT, 256>>>(X, H2, ln_ff_g + l * DIM, ln_ff_b + l * DIM);
    }

    head_kernel<<<BATCH, 256>>>(X, out_w, out_b, out);
}

// round 15
// speedup vs baseline: 3.3514x; 2.7260x over previous
#include <cuda_runtime.h>
#include <cuda_fp16.h>
#include <mma.h>
using namespace nvcuda;

#define DIM   1024
#define TOK   71
#define BATCH 1024
#define BT    (BATCH * TOK)   /* 72704 = 568*128 */
#define LAYERS 12

__device__ float g_x  [(size_t)BT * DIM];
__device__ float g_y  [3 * (size_t)BT * DIM];
__device__ float g_att[(size_t)BATCH * TOK * 72];
__device__ float g_h  [(size_t)BT * 2 * DIM];
__device__ float g_h2 [(size_t)BT * DIM];
// fp16 weight copies
__device__ __half g_qkv_h[(size_t)LAYERS * 3 * DIM * DIM];   // [L][3][K=D][N=D] (layout preserved)
__device__ __half g_l1_h [(size_t)LAYERS * 2 * DIM * DIM];   // [L][N=2D][K=D]
__device__ __half g_l2_h [(size_t)LAYERS * 2 * DIM * DIM];   // [L][N=D][K=2D]

// ---- fp32 -> fp16 weight conversion ----
__global__ __launch_bounds__(256) void conv_half_kernel(
    const float* __restrict__ w, __half* __restrict__ h)
{
    size_t i = ((size_t)blockIdx.x * 256 + threadIdx.x) * 4;
    float4 v = *(const float4*)(w + i);
    __half2* hp = (__half2*)(h + i);
    hp[0] = __floats2half2_rn(v.x, v.y);
    hp[1] = __floats2half2_rn(v.z, v.w);
}

__device__ __forceinline__ float blockSum256(float v, float* buf) {
    #pragma unroll
    for (int o = 16; o > 0; o >>= 1) v += __shfl_xor_sync(0xffffffffu, v, o);
    int lane = threadIdx.x & 31, w = threadIdx.x >> 5;
    if (lane == 0) buf[w] = v;
    __syncthreads();
    if (threadIdx.x == 0) { float s = 0.f;
        #pragma unroll
        for (int i = 0; i < 8; i++) s += buf[i];
        buf[0] = s; }
    __syncthreads();
    float r = buf[0];
    __syncthreads();
    return r;
}

// ---- embedding + LN ----
__global__ __launch_bounds__(256) void embed_ln_kernel(
    const int* __restrict__ fen, const int* __restrict__ mv,
    const float* __restrict__ rank_emb, const float* __restrict__ file_emb,
    const float* __restrict__ fen_emb,  const float* __restrict__ move_emb,
    const float* __restrict__ g, const float* __restrict__ bb,
    float* __restrict__ X)
{
    __shared__ float buf[8];
    int row = blockIdx.x, b = row / TOK, t = row % TOK, d0 = threadIdx.x * 4;
    float e[4];
    if (t < 64) {
        int i1 = fen[b * 133 + t], i2 = fen[b * 133 + 64 + t];
        float4 f1 = *(const float4*)(fen_emb  + (size_t)i1 * DIM + d0);
        float4 f2 = *(const float4*)(fen_emb  + (size_t)i2 * DIM + d0);
        float4 rr = *(const float4*)(rank_emb + (size_t)(t >> 3) * DIM + d0);
        float4 ff = *(const float4*)(file_emb + (size_t)(t & 7)  * DIM + d0);
        e[0] = 0.5f * (f1.x + f2.x + rr.x + ff.x);
        e[1] = 0.5f * (f1.y + f2.y + rr.y + ff.y);
        e[2] = 0.5f * (f1.z + f2.z + rr.z + ff.z);
        e[3] = 0.5f * (f1.w + f2.w + rr.w + ff.w);
    } else if (t < 69) {
        int i1 = fen[b * 133 + 64 + t];
        float4 f1 = *(const float4*)(fen_emb + (size_t)i1 * DIM + d0);
        e[0] = f1.x; e[1] = f1.y; e[2] = f1.z; e[3] = f1.w;
    } else {
        int j = t - 69, p = mv[b * 2 + j];
        float4 rr = *(const float4*)(rank_emb + (size_t)(p >> 3) * DIM + d0);
        float4 ff = *(const float4*)(file_emb + (size_t)(p & 7)  * DIM + d0);
        float4 mm = *(const float4*)(move_emb + (size_t)j * DIM + d0);
        e[0] = 0.58f * (rr.x + ff.x + mm.x);
        e[1] = 0.58f * (rr.y + ff.y + mm.y);
        e[2] = 0.58f * (rr.z + ff.z + mm.z);
        e[3] = 0.58f * (rr.w + ff.w + mm.w);
    }
    float s  = blockSum256(e[0] + e[1] + e[2] + e[3], buf);
    float sq = blockSum256(e[0]*e[0] + e[1]*e[1] + e[2]*e[2] + e[3]*e[3], buf);
    float m = s * (1.f / DIM);
    float rs = rsqrtf(fmaxf(sq * (1.f / DIM) - m * m, 0.f) + 1e-5f);
    float4 gg = *(const float4*)(g + d0), bv = *(const float4*)(bb + d0);
    float4 o;
    o.x = (e[0] - m) * rs * gg.x + bv.x;
    o.y = (e[1] - m) * rs * gg.y + bv.y;
    o.z = (e[2] - m) * rs * gg.z + bv.z;
    o.w = (e[3] - m) * rs * gg.w + bv.w;
    *(float4*)(X + (size_t)row * DIM + d0) = o;
}

// ---- in-place row LN ----
__global__ __launch_bounds__(256) void ln_rows_kernel(
    float* __restrict__ data, const float* __restrict__ g, const float* __restrict__ bb)
{
    __shared__ float buf[8];
    size_t base = (size_t)blockIdx.x * DIM;
    int d0 = threadIdx.x * 4;
    float4 v = *(float4*)(data + base + d0);
    float s  = blockSum256(v.x + v.y + v.z + v.w, buf);
    float sq = blockSum256(v.x*v.x + v.y*v.y + v.z*v.z + v.w*v.w, buf);
    float m = s * (1.f / DIM);
    float rs = rsqrtf(fmaxf(sq * (1.f / DIM) - m * m, 0.f) + 1e-5f);
    float4 gg = *(const float4*)(g + d0), bv = *(const float4*)(bb + d0);
    v.x = (v.x - m) * rs * gg.x + bv.x;
    v.y = (v.y - m) * rs * gg.y + bv.y;
    v.z = (v.z - m) * rs * gg.z + bv.z;
    v.w = (v.w - m) * rs * gg.w + bv.w;
    *(float4*)(data + base + d0) = v;
}

// ---- x = 0.7*(x + LN(y)) ----
__global__ __launch_bounds__(256) void ln_res_kernel(
    float* __restrict__ X, const float* __restrict__ Y,
    const float* __restrict__ g, const float* __restrict__ bb)
{
    __shared__ float buf[8];
    size_t base = (size_t)blockIdx.x * DIM;
    int d0 = threadIdx.x * 4;
    float4 y = *(const float4*)(Y + base + d0);
    float s  = blockSum256(y.x + y.y + y.z + y.w, buf);
    float sq = blockSum256(y.x*y.x + y.y*y.y + y.z*y.z + y.w*y.w, buf);
    float m = s * (1.f / DIM);
    float rs = rsqrtf(fmaxf(sq * (1.f / DIM) - m * m, 0.f) + 1e-5f);
    float4 gg = *(const float4*)(g + d0), bv = *(const float4*)(bb + d0);
    float4 x = *(float4*)(X + base + d0);
    x.x = 0.7f * (x.x + ((y.x - m) * rs * gg.x + bv.x));
    x.y = 0.7f * (x.y + ((y.y - m) * rs * gg.y + bv.y));
    x.z = 0.7f * (x.z + ((y.z - m) * rs * gg.z + bv.z));
    x.w = 0.7f * (x.w + ((y.w - m) * rs * gg.w + bv.w));
    *(float4*)(X + base + d0) = x;
}

// ============================================================================
// fp16 wmma GEMM (fp32 accumulate): C[M,N] = A[M,K] @ B  (A fp32, W fp16)
//   TRANSB=false: B = W[K,N] row-major; TRANSB=true: B = W[N,K] (C = A @ W^T).
//   LEAKY: fused leaky_relu(0.2).
// 128x128 CTA tile, BK=32, double-buffered static smem (<=41KB, 2 CTAs/SM),
// register prefetch of next slab, 1 sync per slab, 16x16x16 HMMA fragments.
// Warp grid 4x2 (warp tile 32 m x 64 n). M%128==0, N%128==0, K%32==0.
// ============================================================================
template <bool TRANSB, bool LEAKY>
__global__ __launch_bounds__(256, 2) void gemm_fp16(
    const float* __restrict__ A, const __half* __restrict__ W,
    float* __restrict__ C, int M, int N, int K)
{
    constexpr int ASZ = 128 * 40;                       // halves per buffer
    constexpr int BSZ = TRANSB ? 128 * 40 : 32 * 136;
    __shared__ __half As[2 * ASZ];
    __shared__ __half Bs[2 * BSZ];

    if (gridDim.z > 1) {
        W += (size_t)blockIdx.z * K * N;
        C += (size_t)blockIdx.z * M * N;
    }
    const int m0 = blockIdx.y * 128, n0 = blockIdx.x * 128;
    const int tid = threadIdx.x, warp = tid >> 5;
    const int wm = warp & 3, wn = warp >> 2;

    wmma::fragment<wmma::accumulator, 16, 16, 16, float> acc[2][4];
    #pragma unroll
    for (int i = 0; i < 2; i++)
        #pragma unroll
        for (int j = 0; j < 4; j++) wmma::fill_fragment(acc[i][j], 0.f);

    float4 ra[4];
    uint4  rb[2];

    auto loadTiles = [&](int k0) {
        #pragma unroll
        for (int q = 0; q < 4; q++) {                   // A: 128x32 fp32
            int id = tid + q * 256;
            ra[q] = *(const float4*)(A + (size_t)(m0 + (id >> 3)) * K + k0 + (id & 7) * 4);
        }
        if constexpr (TRANSB) {                         // W[N,K] fp16: 128 rows x 32 k
            #pragma unroll
            for (int q = 0; q < 2; q++) {
                int id = tid + q * 256;
                rb[q] = *(const uint4*)(W + (size_t)(n0 + (id >> 2)) * K + k0 + (id & 3) * 8);
            }
        } else {                                        // W[K,N] fp16: 32 rows x 128 n
            #pragma unroll
            for (int q = 0; q < 2; q++) {
                int id = tid + q * 256;
                rb[q] = *(const uint4*)(W + (size_t)(k0 + (id >> 4)) * N + n0 + (id & 15) * 8);
            }
        }
    };
    auto storeTiles = [&](__half* ad, __half* bd) {
        #pragma unroll
        for (int q = 0; q < 4; q++) {
            int id = tid + q * 256, r = id >> 3, c = (id & 7) * 4;
            __half2* p = (__half2*)(ad + r * 40 + c);
            p[0] = __floats2half2_rn(ra[q].x, ra[q].y);
            p[1] = __floats2half2_rn(ra[q].z, ra[q].w);
        }
        if constexpr (TRANSB) {
            #pragma unroll
            for (int q = 0; q < 2; q++) {
                int id = tid + q * 256, r = id >> 2, c = (id & 3) * 8;
                *(uint4*)(bd + r * 40 + c) = rb[q];
            }
        } else {
            #pragma unroll
            for (int q = 0; q < 2; q++) {
                int id = tid + q * 256, r = id >> 4, c = (id & 15) * 8;
                *(uint4*)(bd + r * 136 + c) = rb[q];
            }
        }
    };

    loadTiles(0);
    storeTiles(As, Bs);
    __syncthreads();

    const int KT = K >> 5;
    for (int kt = 0; kt < KT; kt++) {
        if (kt + 1 < KT) loadTiles((kt + 1) << 5);      // prefetch next slab

        const __half* Ac = As + (kt & 1) * ASZ;
        const __half* Bc = Bs + (kt & 1) * BSZ;
        #pragma unroll
        for (int ks = 0; ks < 32; ks += 16) {
            wmma::fragment<wmma::matrix_a, 16, 16, 16, __half, wmma::row_major> af[2];
            wmma::load_matrix_sync(af[0], Ac + (wm * 32 + 0)  * 40 + ks, 40);
            wmma::load_matrix_sync(af[1], Ac + (wm * 32 + 16) * 40 + ks, 40);
            #pragma unroll
            for (int j = 0; j < 4; j++) {
                if constexpr (TRANSB) {
                    wmma::fragment<wmma::matrix_b, 16, 16, 16, __half, wmma::col_major> bf;
                    wmma::load_matrix_sync(bf, Bc + (wn * 64 + j * 16) * 40 + ks, 40);
                    wmma::mma_sync(acc[0][j], af[0], bf, acc[0][j]);
                    wmma::mma_sync(acc[1][j], af[1], bf, acc[1][j]);
                } else {
                    wmma::fragment<wmma::matrix_b, 16, 16, 16, __half, wmma::row_major> bf;
                    wmma::load_matrix_sync(bf, Bc + ks * 136 + wn * 64 + j * 16, 136);
                    wmma::mma_sync(acc[0][j], af[0], bf, acc[0][j]);
                    wmma::mma_sync(acc[1][j], af[1], bf, acc[1][j]);
                }
            }
        }
        if (kt + 1 < KT)
            storeTiles(As + ((kt + 1) & 1) * ASZ, Bs + ((kt + 1) & 1) * BSZ);
        __syncthreads();
    }

    #pragma unroll
    for (int i = 0; i < 2; i++)
        #pragma unroll
        for (int j = 0; j < 4; j++) {
            if constexpr (LEAKY) {
                #pragma unroll
                for (int t = 0; t < acc[i][j].num_elements; t++) {
                    float x = acc[i][j].x[t];
                    acc[i][j].x[t] = x > 0.f ? x : 0.2f * x;
                }
            }
            wmma::store_matrix_sync(
                C + (size_t)(m0 + wm * 32 + i * 16) * N + n0 + wn * 64 + j * 16,
                acc[i][j], N, wmma::mem_row_major);
        }
}

// ---- scores + softmax per batch item ----
__global__ __launch_bounds__(256) void scores_softmax_kernel(
    const float* __restrict__ Q, const float* __restrict__ Km, float* __restrict__ ATT)
{
    __shared__ float sm[5280];
    float* qs = sm;
    float* ks = sm + 2640;
    const int b = blockIdx.x, tid = threadIdx.x;
    const int tx = tid & 15, ty = tid >> 4;

    float acc[5][5];
    #pragma unroll
    for (int i = 0; i < 5; i++)
        #pragma unroll
        for (int j = 0; j < 5; j++) acc[i][j] = 0.f;

    for (int kc = 0; kc < DIM; kc += 32) {
        __syncthreads();
        for (int idx = tid; idx < TOK * 32; idx += 256) {
            int r = idx >> 5, c = idx & 31;
            size_t gb = ((size_t)b * TOK + r) * DIM + kc + c;
            qs[r * 33 + c] = Q[gb];
            ks[r * 33 + c] = Km[gb];
        }
        __syncthreads();
        #pragma unroll 8
        for (int kk = 0; kk < 32; kk++) {
            float qv[5], kv[5];
            #pragma unroll
            for (int i = 0; i < 5; i++) qv[i] = (ty + 16 * i < TOK) ? qs[(ty + 16 * i) * 33 + kk] : 0.f;
            #pragma unroll
            for (int j = 0; j < 5; j++) kv[j] = (tx + 16 * j < TOK) ? ks[(tx + 16 * j) * 33 + kk] : 0.f;
            #pragma unroll
            for (int i = 0; i < 5; i++)
                #pragma unroll
                for (int j = 0; j < 5; j++) acc[i][j] += qv[i] * kv[j];
        }
    }
    __syncthreads();
    #pragma unroll
    for (int i = 0; i < 5; i++)
        #pragma unroll
        for (int j = 0; j < 5; j++) {
            int r = ty + 16 * i, c = tx + 16 * j;
            if (r < TOK && c < TOK) sm[r * 72 + c] = acc[i][j] * 0.03125f;
        }
    __syncthreads();

    const int lane = tid & 31, w = tid >> 5;
    for (int r = w; r < TOK; r += 8) {
        float v[3], p[3], mx = -1e30f;
        #pragma unroll
        for (int q = 0; q < 3; q++) {
            int c = lane + q * 32;
            v[q] = (c < TOK) ? sm[r * 72 + c] : -1e30f;
            mx = fmaxf(mx, v[q]);
        }
        #pragma unroll
        for (int o = 16; o > 0; o >>= 1) mx = fmaxf(mx, __shfl_xor_sync(0xffffffffu, mx, o));
        float sum = 0.f;
        #pragma unroll
        for (int q = 0; q < 3; q++) {
            int c = lane + q * 32;
            p[q] = (c < TOK) ? __expf(v[q] - mx) : 0.f;
            sum += p[q];
        }
        #pragma unroll
        for (int o = 16; o > 0; o >>= 1) sum += __shfl_xor_sync(0xffffffffu, sum, o);
        float inv = 1.f / sum;
        #pragma unroll
        for (int q = 0; q < 3; q++) {
            int c = lane + q * 32;
            if (c < TOK) ATT[(size_t)b * (TOK * 72) + r * 72 + c] = p[q] * inv;
        }
    }
}

// ---- AO = ATT @ V ----
__global__ __launch_bounds__(128) void av_kernel(
    const float* __restrict__ ATT, const float* __restrict__ V, float* __restrict__ AO)
{
    __shared__ float att_s[TOK * 72];
    const int b = blockIdx.y;
    const int d = blockIdx.x * 128 + threadIdx.x;
    for (int i = threadIdx.x; i < TOK * TOK; i += 128) {
        int t = i / TOK, s = i - t * TOK;
        att_s[t * 72 + s] = ATT[(size_t)b * (TOK * 72) + t * 72 + s];
    }
    __syncthreads();
    float acc[TOK];
    #pragma unroll
    for (int t = 0; t < TOK; t++) acc[t] = 0.f;
    for (int s = 0; s < TOK; s++) {
        float vv = V[((size_t)b * TOK + s) * DIM + d];
        #pragma unroll
        for (int t = 0; t < TOK; t++) acc[t] += att_s[t * 72 + s] * vv;
    }
    #pragma unroll
    for (int t = 0; t < TOK; t++)
        AO[((size_t)b * TOK + t) * DIM + d] = acc[t];
}

// ---- head ----
__global__ __launch_bounds__(256) void head_kernel(
    const float* __restrict__ X, const float* __restrict__ w,
    const float* __restrict__ bias, float* __restrict__ out)
{
    __shared__ float buf[8];
    const int b = blockIdx.x;
    float s = 0.f;
    for (int i = threadIdx.x; i < 2 * DIM; i += 256) {
        float xv = (i < DIM) ? X[((size_t)b * TOK + 69) * DIM + i]
                             : X[((size_t)b * TOK + 70) * DIM + i - DIM];
        s += xv * w[i];
    }
    s = blockSum256(s, buf);
    if (threadIdx.x == 0) out[b] = 1.f / (1.f + __expf(-(s + bias[0])));
}

extern "C" void kernel_launch(void* const* d_in, const int* in_sizes, int n_in,
                              void* d_out, int out_size)
{
    const int*   fen       = (const int*)  d_in[0];
    const int*   mv        = (const int*)  d_in[1];
    const float* rank_emb  = (const float*)d_in[2];
    const float* file_emb  = (const float*)d_in[3];
    const float* fen_emb   = (const float*)d_in[4];
    const float* move_emb  = (const float*)d_in[5];
    const float* ln_emb_g  = (const float*)d_in[6];
    const float* ln_emb_b  = (const float*)d_in[7];
    const float* qkv       = (const float*)d_in[8];
    const float* ln_q_g    = (const float*)d_in[9];
    const float* ln_q_b    = (const float*)d_in[10];
    const float* ln_k_g    = (const float*)d_in[11];
    const float* ln_k_b    = (const float*)d_in[12];
    const float* ln_attn_g = (const float*)d_in[13];
    const float* ln_attn_b = (const float*)d_in[14];
    const float* lin1_w    = (const float*)d_in[15];
    const float* lin2_w    = (const float*)d_in[16];
    const float* ln_ff_g   = (const float*)d_in[17];
    const float* ln_ff_b   = (const float*)d_in[18];
    const float* out_w     = (const float*)d_in[19];
    const float* out_b     = (const float*)d_in[20];
    float* out = (float*)d_out;

    float *X, *Y, *ATT, *H, *H2;
    __half *QW, *L1, *L2;
    cudaGetSymbolAddress((void**)&X,   g_x);
    cudaGetSymbolAddress((void**)&Y,   g_y);
    cudaGetSymbolAddress((void**)&ATT, g_att);
    cudaGetSymbolAddress((void**)&H,   g_h);
    cudaGetSymbolAddress((void**)&H2,  g_h2);
    cudaGetSymbolAddress((void**)&QW,  g_qkv_h);
    cudaGetSymbolAddress((void**)&L1,  g_l1_h);
    cudaGetSymbolAddress((void**)&L2,  g_l2_h);

    // one-time-per-launch weight conversion (graph-capturable kernels)
    conv_half_kernel<<<(LAYERS * 3 * DIM * DIM) / 1024, 256>>>(qkv,    QW);
    conv_half_kernel<<<(LAYERS * 2 * DIM * DIM) / 1024, 256>>>(lin1_w, L1);
    conv_half_kernel<<<(LAYERS * 2 * DIM * DIM) / 1024, 256>>>(lin2_w, L2);

    embed_ln_kernel<<<BT, 256>>>(fen, mv, rank_emb, file_emb, fen_emb, move_emb,
                                 ln_emb_g, ln_emb_b, X);

    for (int l = 0; l < LAYERS; l++) {
        // QKV: Y[z] = X @ qkv[l][z], W row-major [K=D,N=D], 3 slabs via grid.z
        gemm_fp16<false, false><<<dim3(DIM / 128, BT / 128, 3), 256>>>(
            X, QW + (size_t)l * 3 * DIM * DIM, Y, BT, DIM, DIM);

        ln_rows_kernel<<<BT, 256>>>(Y,                    ln_q_g + l * DIM, ln_q_b + l * DIM);
        ln_rows_kernel<<<BT, 256>>>(Y + (size_t)BT * DIM, ln_k_g + l * DIM, ln_k_b + l * DIM);

        scores_softmax_kernel<<<BATCH, 256>>>(Y, Y + (size_t)BT * DIM, ATT);
        av_kernel<<<dim3(DIM / 128, BATCH), 128>>>(ATT, Y + 2 * (size_t)BT * DIM, H2);

        ln_res_kernel<<<BT, 256>>>(X, H2, ln_attn_g + l * DIM, ln_attn_b + l * DIM);

        // FF: H = leaky(X @ lin1^T) [BT,2D]; H2 = leaky(H @ lin2^T) [BT,D]
        gemm_fp16<true, true><<<dim3(2 * DIM / 128, BT / 128, 1), 256>>>(
            X, L1 + (size_t)l * 2 * DIM * DIM, H, BT, 2 * DIM, DIM);
        gemm_fp16<true, true><<<dim3(DIM / 128, BT / 128, 1), 256>>>(
            H, L2 + (size_t)l * 2 * DIM * DIM, H2, BT, DIM, 2 * DIM);

        ln_res_kernel<<<BT, 256>>>(X, H2, ln_ff_g + l * DIM, ln_ff_b + l * DIM);
    }

    head_kernel<<<BATCH, 256>>>(X, out_w, out_b, out);
}

// round 17
// speedup vs baseline: 4.2861x; 1.2789x over previous
#include <cuda_runtime.h>
#include <cuda_fp16.h>
#include <mma.h>
using namespace nvcuda;

#define DIM   1024
#define TOK   71
#define BATCH 1024
#define BT    (BATCH * TOK)   /* 72704 = 568*128 */
#define LAYERS 12

// ---------------- scratch ----------------
__device__ float  g_x  [(size_t)BT * DIM];                 // residual fp32
__device__ __half g_x16[(size_t)BT * DIM];                 // fp16 mirror (GEMM A)
__device__ __half g_y16[3 * (size_t)BT * DIM];             // q,k,v fp16
__device__ __half g_att16[(size_t)BATCH * 80 * 80];        // P fp16 padded
__device__ __half g_h16[(size_t)BT * 2 * DIM];             // FF hidden fp16
__device__ float  g_h2 [(size_t)BT * DIM];                 // FF2 out fp32
__device__ float  g_o  [(size_t)BATCH * 80 * DIM];         // attn out fp32 padded
__device__ __half g_qkv_h[(size_t)LAYERS * 3 * DIM * DIM]; // [L][3][K][N]
__device__ __half g_l1_h [(size_t)LAYERS * 2 * DIM * DIM]; // [L][N=2D][K=D]
__device__ __half g_l2_h [(size_t)LAYERS * 2 * DIM * DIM]; // [L][N=D][K=2D]

// ---- fp32 -> fp16 weight conversion ----
__global__ __launch_bounds__(256) void conv_half_kernel(
    const float* __restrict__ w, __half* __restrict__ h)
{
    size_t i = ((size_t)blockIdx.x * 256 + threadIdx.x) * 4;
    float4 v = *(const float4*)(w + i);
    __half2* hp = (__half2*)(h + i);
    hp[0] = __floats2half2_rn(v.x, v.y);
    hp[1] = __floats2half2_rn(v.z, v.w);
}

__device__ __forceinline__ float blockSum256(float v, float* buf) {
    #pragma unroll
    for (int o = 16; o > 0; o >>= 1) v += __shfl_xor_sync(0xffffffffu, v, o);
    int lane = threadIdx.x & 31, w = threadIdx.x >> 5;
    if (lane == 0) buf[w] = v;
    __syncthreads();
    if (threadIdx.x == 0) { float s = 0.f;
        #pragma unroll
        for (int i = 0; i < 8; i++) s += buf[i];
        buf[0] = s; }
    __syncthreads();
    float r = buf[0];
    __syncthreads();
    return r;
}

// ---- embedding + LN -> X fp32 + X16 ----
__global__ __launch_bounds__(256) void embed_ln_kernel(
    const int* __restrict__ fen, const int* __restrict__ mv,
    const float* __restrict__ rank_emb, const float* __restrict__ file_emb,
    const float* __restrict__ fen_emb,  const float* __restrict__ move_emb,
    const float* __restrict__ g, const float* __restrict__ bb,
    float* __restrict__ X, __half* __restrict__ X16)
{
    __shared__ float buf[8];
    int row = blockIdx.x, b = row / TOK, t = row % TOK, d0 = threadIdx.x * 4;
    float e[4];
    if (t < 64) {
        int i1 = fen[b * 133 + t], i2 = fen[b * 133 + 64 + t];
        float4 f1 = *(const float4*)(fen_emb  + (size_t)i1 * DIM + d0);
        float4 f2 = *(const float4*)(fen_emb  + (size_t)i2 * DIM + d0);
        float4 rr = *(const float4*)(rank_emb + (size_t)(t >> 3) * DIM + d0);
        float4 ff = *(const float4*)(file_emb + (size_t)(t & 7)  * DIM + d0);
        e[0] = 0.5f * (f1.x + f2.x + rr.x + ff.x);
        e[1] = 0.5f * (f1.y + f2.y + rr.y + ff.y);
        e[2] = 0.5f * (f1.z + f2.z + rr.z + ff.z);
        e[3] = 0.5f * (f1.w + f2.w + rr.w + ff.w);
    } else if (t < 69) {
        int i1 = fen[b * 133 + 64 + t];
        float4 f1 = *(const float4*)(fen_emb + (size_t)i1 * DIM + d0);
        e[0] = f1.x; e[1] = f1.y; e[2] = f1.z; e[3] = f1.w;
    } else {
        int j = t - 69, p = mv[b * 2 + j];
        float4 rr = *(const float4*)(rank_emb + (size_t)(p >> 3) * DIM + d0);
        float4 ff = *(const float4*)(file_emb + (size_t)(p & 7)  * DIM + d0);
        float4 mm = *(const float4*)(move_emb + (size_t)j * DIM + d0);
        e[0] = 0.58f * (rr.x + ff.x + mm.x);
        e[1] = 0.58f * (rr.y + ff.y + mm.y);
        e[2] = 0.58f * (rr.z + ff.z + mm.z);
        e[3] = 0.58f * (rr.w + ff.w + mm.w);
    }
    float s  = blockSum256(e[0] + e[1] + e[2] + e[3], buf);
    float sq = blockSum256(e[0]*e[0] + e[1]*e[1] + e[2]*e[2] + e[3]*e[3], buf);
    float m = s * (1.f / DIM);
    float rs = rsqrtf(fmaxf(sq * (1.f / DIM) - m * m, 0.f) + 1e-5f);
    float4 gg = *(const float4*)(g + d0), bv = *(const float4*)(bb + d0);
    float4 o;
    o.x = (e[0] - m) * rs * gg.x + bv.x;
    o.y = (e[1] - m) * rs * gg.y + bv.y;
    o.z = (e[2] - m) * rs * gg.z + bv.z;
    o.w = (e[3] - m) * rs * gg.w + bv.w;
    *(float4*)(X + (size_t)row * DIM + d0) = o;
    __half2* xp = (__half2*)(X16 + (size_t)row * DIM + d0);
    xp[0] = __floats2half2_rn(o.x, o.y);
    xp[1] = __floats2half2_rn(o.z, o.w);
}

// ---- in-place fp16 row LN (q,k) ----
__global__ __launch_bounds__(256) void ln16_kernel(
    __half* __restrict__ data, const float* __restrict__ g, const float* __restrict__ bb)
{
    __shared__ float buf[8];
    size_t base = (size_t)blockIdx.x * DIM;
    int d0 = threadIdx.x * 4;
    __half2* p = (__half2*)(data + base + d0);
    float2 a = __half22float2(p[0]), c = __half22float2(p[1]);
    float s  = blockSum256(a.x + a.y + c.x + c.y, buf);
    float sq = blockSum256(a.x*a.x + a.y*a.y + c.x*c.x + c.y*c.y, buf);
    float m = s * (1.f / DIM);
    float rs = rsqrtf(fmaxf(sq * (1.f / DIM) - m * m, 0.f) + 1e-5f);
    float4 gg = *(const float4*)(g + d0), bv = *(const float4*)(bb + d0);
    p[0] = __floats2half2_rn((a.x - m) * rs * gg.x + bv.x, (a.y - m) * rs * gg.y + bv.y);
    p[1] = __floats2half2_rn((c.x - m) * rs * gg.z + bv.z, (c.y - m) * rs * gg.w + bv.w);
}

// ---- x = 0.7*(x + LN(y)); updates X fp32 and X16; pad=1 -> Y is [B][80][D] ----
__global__ __launch_bounds__(256) void ln_res_kernel(
    float* __restrict__ X, __half* __restrict__ X16, const float* __restrict__ Y,
    const float* __restrict__ g, const float* __restrict__ bb, int pad)
{
    __shared__ float buf[8];
    int row = blockIdx.x;
    size_t ybase = pad ? (((size_t)(row / TOK)) * 80 + (row % TOK)) * DIM
                       : (size_t)row * DIM;
    size_t base = (size_t)row * DIM;
    int d0 = threadIdx.x * 4;
    float4 y = *(const float4*)(Y + ybase + d0);
    float s  = blockSum256(y.x + y.y + y.z + y.w, buf);
    float sq = blockSum256(y.x*y.x + y.y*y.y + y.z*y.z + y.w*y.w, buf);
    float m = s * (1.f / DIM);
    float rs = rsqrtf(fmaxf(sq * (1.f / DIM) - m * m, 0.f) + 1e-5f);
    float4 gg = *(const float4*)(g + d0), bv = *(const float4*)(bb + d0);
    float4 x = *(float4*)(X + base + d0);
    x.x = 0.7f * (x.x + ((y.x - m) * rs * gg.x + bv.x));
    x.y = 0.7f * (x.y + ((y.y - m) * rs * gg.y + bv.y));
    x.z = 0.7f * (x.z + ((y.z - m) * rs * gg.z + bv.z));
    x.w = 0.7f * (x.w + ((y.w - m) * rs * gg.w + bv.w));
    *(float4*)(X + base + d0) = x;
    __half2* xp = (__half2*)(X16 + base + d0);
    xp[0] = __floats2half2_rn(x.x, x.y);
    xp[1] = __floats2half2_rn(x.z, x.w);
}

// ============================================================================
// fp16 wmma GEMM, fp32 acc. A fp16 [M][K]. TRANSB: W[N][K] else W[K][N].
// OUTHALF: write fp16 via smem staging (safe frag layout). LEAKY fused.
// 128x128 tile, BK=32, double-buffered dynamic smem, reg prefetch, 2 CTA/SM.
// ============================================================================
template <bool TRANSB, bool LEAKY, bool OUTHALF>
__global__ __launch_bounds__(256, 2) void gemm_fp16(
    const __half* __restrict__ A, const __half* __restrict__ W,
    float* __restrict__ Cf, __half* __restrict__ Ch, int M, int N, int K)
{
    constexpr int ASZ = 128 * 40;                       // halves per buffer
    constexpr int BSZ = TRANSB ? 128 * 40 : 32 * 136;
    extern __shared__ char dsm[];
    __half* As = (__half*)dsm;                          // 2*ASZ halves
    __half* Bs = (__half*)(dsm + 2 * ASZ * 2);          // 2*BSZ halves
    float*  stg = (float*)(dsm + 2 * ASZ * 2 + 2 * BSZ * 2);  // 8*320 floats

    if (gridDim.z > 1) {
        size_t zo = (size_t)blockIdx.z;
        W += zo * (size_t)K * N;
        if (OUTHALF) Ch += zo * (size_t)M * N; else Cf += zo * (size_t)M * N;
    }
    const int m0 = blockIdx.y * 128, n0 = blockIdx.x * 128;
    const int tid = threadIdx.x, warp = tid >> 5, lane = tid & 31;
    const int wm = warp & 3, wn = warp >> 2;

    wmma::fragment<wmma::accumulator, 16, 16, 16, float> acc[2][4];
    #pragma unroll
    for (int i = 0; i < 2; i++)
        #pragma unroll
        for (int j = 0; j < 4; j++) wmma::fill_fragment(acc[i][j], 0.f);

    uint4 ra[2], rb[2];
    auto loadTiles = [&](int k0) {
        #pragma unroll
        for (int q = 0; q < 2; q++) {                   // A: 128x32 halves
            int id = tid + q * 256;
            ra[q] = *(const uint4*)(A + (size_t)(m0 + (id >> 2)) * K + k0 + (id & 3) * 8);
        }
        if constexpr (TRANSB) {
            #pragma unroll
            for (int q = 0; q < 2; q++) {
                int id = tid + q * 256;
                rb[q] = *(const uint4*)(W + (size_t)(n0 + (id >> 2)) * K + k0 + (id & 3) * 8);
            }
        } else {
            #pragma unroll
            for (int q = 0; q < 2; q++) {
                int id = tid + q * 256;
                rb[q] = *(const uint4*)(W + (size_t)(k0 + (id >> 4)) * N + n0 + (id & 15) * 8);
            }
        }
    };
    auto storeTiles = [&](__half* ad, __half* bd) {
        #pragma unroll
        for (int q = 0; q < 2; q++) {
            int id = tid + q * 256;
            *(uint4*)(ad + (id >> 2) * 40 + (id & 3) * 8) = ra[q];
        }
        if constexpr (TRANSB) {
            #pragma unroll
            for (int q = 0; q < 2; q++) {
                int id = tid + q * 256;
                *(uint4*)(bd + (id >> 2) * 40 + (id & 3) * 8) = rb[q];
            }
        } else {
            #pragma unroll
            for (int q = 0; q < 2; q++) {
                int id = tid + q * 256;
                *(uint4*)(bd + (id >> 4) * 136 + (id & 15) * 8) = rb[q];
            }
        }
    };

    loadTiles(0);
    storeTiles(As, Bs);
    __syncthreads();

    const int KT = K >> 5;
    for (int kt = 0; kt < KT; kt++) {
        if (kt + 1 < KT) loadTiles((kt + 1) << 5);
        const __half* Ac = As + (kt & 1) * ASZ;
        const __half* Bc = Bs + (kt & 1) * BSZ;
        #pragma unroll
        for (int ks = 0; ks < 32; ks += 16) {
            wmma::fragment<wmma::matrix_a, 16, 16, 16, __half, wmma::row_major> af[2];
            wmma::load_matrix_sync(af[0], Ac + (wm * 32 + 0)  * 40 + ks, 40);
            wmma::load_matrix_sync(af[1], Ac + (wm * 32 + 16) * 40 + ks, 40);
            #pragma unroll
            for (int j = 0; j < 4; j++) {
                if constexpr (TRANSB) {
                    wmma::fragment<wmma::matrix_b, 16, 16, 16, __half, wmma::col_major> bf;
                    wmma::load_matrix_sync(bf, Bc + (wn * 64 + j * 16) * 40 + ks, 40);
                    wmma::mma_sync(acc[0][j], af[0], bf, acc[0][j]);
                    wmma::mma_sync(acc[1][j], af[1], bf, acc[1][j]);
                } else {
                    wmma::fragment<wmma::matrix_b, 16, 16, 16, __half, wmma::row_major> bf;
                    wmma::load_matrix_sync(bf, Bc + ks * 136 + wn * 64 + j * 16, 136);
                    wmma::mma_sync(acc[0][j], af[0], bf, acc[0][j]);
                    wmma::mma_sync(acc[1][j], af[1], bf, acc[1][j]);
                }
            }
        }
        if (kt + 1 < KT)
            storeTiles(As + ((kt + 1) & 1) * ASZ, Bs + ((kt + 1) & 1) * BSZ);
        __syncthreads();
    }

    float* sw = stg + warp * 320;                       // 16x20 staging tile
    #pragma unroll
    for (int i = 0; i < 2; i++)
        #pragma unroll
        for (int j = 0; j < 4; j++) {
            if constexpr (OUTHALF) {
                wmma::store_matrix_sync(sw, acc[i][j], 20, wmma::mem_row_major);
                __syncwarp();
                int r = lane >> 1, c0 = (lane & 1) * 8;
                union { uint4 u; __half2 h[4]; } t;
                #pragma unroll
                for (int k2 = 0; k2 < 4; k2++) {
                    float v0 = sw[r * 20 + c0 + k2 * 2];
                    float v1 = sw[r * 20 + c0 + k2 * 2 + 1];
                    if (LEAKY) {
                        v0 = v0 > 0.f ? v0 : 0.2f * v0;
                        v1 = v1 > 0.f ? v1 : 0.2f * v1;
                    }
                    t.h[k2] = __floats2half2_rn(v0, v1);
                }
                *(uint4*)(Ch + (size_t)(m0 + wm * 32 + i * 16 + r) * N
                              + n0 + wn * 64 + j * 16 + c0) = t.u;
                __syncwarp();
            } else {
                if (LEAKY) {
                    #pragma unroll
                    for (int t2 = 0; t2 < acc[i][j].num_elements; t2++) {
                        float x = acc[i][j].x[t2];
                        acc[i][j].x[t2] = x > 0.f ? x : 0.2f * x;
                    }
                }
                wmma::store_matrix_sync(
                    Cf + (size_t)(m0 + wm * 32 + i * 16) * N + n0 + wn * 64 + j * 16,
                    acc[i][j], N, wmma::mem_row_major);
            }
        }
}
#define GSMEM(TB) ((2 * 128 * 40 * 2) + 2 * ((TB) ? 128 * 40 : 32 * 136) * 2 + 8 * 320 * 4)

// ============================================================================
// scores+softmax (wmma): per b, S = QK^T/32 on 80x80 padded, softmax -> P fp16
// ============================================================================
__global__ __launch_bounds__(256) void scores_wmma(
    const __half* __restrict__ Qg, const __half* __restrict__ Kg,
    __half* __restrict__ ATT)
{
    __shared__ __align__(16) char smx[27200];
    __half* Qs = (__half*)smx;            // [80][72]
    __half* Ks = (__half*)(smx + 11520);  // [80][72]
    float*  S  = (float*)smx;             // [80][84] (aliases Qs/Ks, used after)
    const int b = blockIdx.x, tid = threadIdx.x, wid = tid >> 5, lane = tid & 31;
    const __half* qb = Qg + (size_t)b * TOK * DIM;
    const __half* kb = Kg + (size_t)b * TOK * DIM;

    wmma::fragment<wmma::accumulator, 16, 16, 16, float> acc[4];
    { int nf = 0;
      for (int f = wid; f < 25; f += 8) { wmma::fill_fragment(acc[nf], 0.f); nf++; } }

    for (int kc = 0; kc < DIM; kc += 64) {
        __syncthreads();
        for (int idx = tid; idx < 640; idx += 256) {
            int r = idx >> 3, c8 = (idx & 7) * 8;
            uint4 z = make_uint4(0, 0, 0, 0);
            *(uint4*)(Qs + r * 72 + c8) =
                (r < TOK) ? *(const uint4*)(qb + (size_t)r * DIM + kc + c8) : z;
            *(uint4*)(Ks + r * 72 + c8) =
                (r < TOK) ? *(const uint4*)(kb + (size_t)r * DIM + kc + c8) : z;
        }
        __syncthreads();
        int nf = 0;
        for (int f = wid; f < 25; f += 8) {
            int fi = f / 5, fj = f % 5;
            #pragma unroll
            for (int ks = 0; ks < 64; ks += 16) {
                wmma::fragment<wmma::matrix_a, 16, 16, 16, __half, wmma::row_major> af;
                wmma::fragment<wmma::matrix_b, 16, 16, 16, __half, wmma::col_major> bf;
                wmma::load_matrix_sync(af, Qs + fi * 16 * 72 + ks, 72);
                wmma::load_matrix_sync(bf, Ks + fj * 16 * 72 + ks, 72);
                wmma::mma_sync(acc[nf], af, bf, acc[nf]);
            }
            nf++;
        }
    }
    __syncthreads();
    { int nf = 0;
      for (int f = wid; f < 25; f += 8) {
          int fi = f / 5, fj = f % 5;
          wmma::store_matrix_sync(S + fi * 16 * 84 + fj * 16, acc[nf], 84,
                                  wmma::mem_row_major);
          nf++;
      } }
    __syncthreads();

    __half* out = ATT + (size_t)b * 6400;
    for (int r = wid; r < 80; r += 8) {
        if (r < TOK) {
            float v[3], mx = -1e30f;
            #pragma unroll
            for (int q = 0; q < 3; q++) {
                int c = lane + q * 32;
                v[q] = (c < TOK) ? S[r * 84 + c] * 0.03125f : -1e30f;
                mx = fmaxf(mx, v[q]);
            }
            #pragma unroll
            for (int o = 16; o > 0; o >>= 1) mx = fmaxf(mx, __shfl_xor_sync(0xffffffffu, mx, o));
            float p[3], sum = 0.f;
            #pragma unroll
            for (int q = 0; q < 3; q++) {
                int c = lane + q * 32;
                p[q] = (c < TOK) ? __expf(v[q] - mx) : 0.f;
                sum += p[q];
            }
            #pragma unroll
            for (int o = 16; o > 0; o >>= 1) sum += __shfl_xor_sync(0xffffffffu, sum, o);
            float inv = 1.f / sum;
            #pragma unroll
            for (int q = 0; q < 3; q++) {
                int c = lane + q * 32;
                if (c < 80) out[r * 80 + c] = __float2half((c < TOK) ? p[q] * inv : 0.f);
            }
        } else {
            #pragma unroll
            for (int q = 0; q < 3; q++) {
                int c = lane + q * 32;
                if (c < 80) out[r * 80 + c] = __float2half(0.f);
            }
        }
    }
}

// ============================================================================
// AV (wmma): per b, O[80][1024] = P[80][80] @ V[80][1024] (V rows>=71 zero)
// ============================================================================
__global__ __launch_bounds__(256) void av_wmma(
    const __half* __restrict__ ATT, const __half* __restrict__ Vg,
    float* __restrict__ O)
{
    __shared__ __align__(16) __half Ps[80 * 80];
    __shared__ __align__(16) __half Vs[80 * 136];
    const int b = blockIdx.x, tid = threadIdx.x, wid = tid >> 5;
    const __half* attb = ATT + (size_t)b * 6400;
    const __half* vb = Vg + (size_t)b * TOK * DIM;

    for (int idx = tid; idx < 800; idx += 256)
        *(uint4*)(Ps + idx * 8) = *(const uint4*)(attb + idx * 8);

    for (int nc = 0; nc < DIM; nc += 128) {
        __syncthreads();
        for (int idx = tid; idx < 1280; idx += 256) {
            int r = idx >> 4, c8 = (idx & 15) * 8;
            uint4 z = make_uint4(0, 0, 0, 0);
            *(uint4*)(Vs + r * 136 + c8) =
                (r < TOK) ? *(const uint4*)(vb + (size_t)r * DIM + nc + c8) : z;
        }
        __syncthreads();
        wmma::fragment<wmma::accumulator, 16, 16, 16, float> acc[5];
        #pragma unroll
        for (int mi = 0; mi < 5; mi++) wmma::fill_fragment(acc[mi], 0.f);
        #pragma unroll
        for (int ks = 0; ks < 80; ks += 16) {
            wmma::fragment<wmma::matrix_b, 16, 16, 16, __half, wmma::row_major> bf;
            wmma::load_matrix_sync(bf, Vs + ks * 136 + wid * 16, 136);
            #pragma unroll
            for (int mi = 0; mi < 5; mi++) {
                wmma::fragment<wmma::matrix_a, 16, 16, 16, __half, wmma::row_major> af;
                wmma::load_matrix_sync(af, Ps + (mi * 16) * 80 + ks, 80);
                wmma::mma_sync(acc[mi], af, bf, acc[mi]);
            }
        }
        #pragma unroll
        for (int mi = 0; mi < 5; mi++)
            wmma::store_matrix_sync(
                O + ((size_t)b * 80 + mi * 16) * DIM + nc + wid * 16,
                acc[mi], DIM, wmma::mem_row_major);
    }
}

// ---- head ----
__global__ __launch_bounds__(256) void head_kernel(
    const float* __restrict__ X, const float* __restrict__ w,
    const float* __restrict__ bias, float* __restrict__ out)
{
    __shared__ float buf[8];
    const int b = blockIdx.x;
    float s = 0.f;
    for (int i = threadIdx.x; i < 2 * DIM; i += 256) {
        float xv = (i < DIM) ? X[((size_t)b * TOK + 69) * DIM + i]
                             : X[((size_t)b * TOK + 70) * DIM + i - DIM];
        s += xv * w[i];
    }
    s = blockSum256(s, buf);
    if (threadIdx.x == 0) out[b] = 1.f / (1.f + __expf(-(s + bias[0])));
}

extern "C" void kernel_launch(void* const* d_in, const int* in_sizes, int n_in,
                              void* d_out, int out_size)
{
    const int*   fen       = (const int*)  d_in[0];
    const int*   mv        = (const int*)  d_in[1];
    const float* rank_emb  = (const float*)d_in[2];
    const float* file_emb  = (const float*)d_in[3];
    const float* fen_emb   = (const float*)d_in[4];
    const float* move_emb  = (const float*)d_in[5];
    const float* ln_emb_g  = (const float*)d_in[6];
    const float* ln_emb_b  = (const float*)d_in[7];
    const float* qkv       = (const float*)d_in[8];
    const float* ln_q_g    = (const float*)d_in[9];
    const float* ln_q_b    = (const float*)d_in[10];
    const float* ln_k_g    = (const float*)d_in[11];
    const float* ln_k_b    = (const float*)d_in[12];
    const float* ln_attn_g = (const float*)d_in[13];
    const float* ln_attn_b = (const float*)d_in[14];
    const float* lin1_w    = (const float*)d_in[15];
    const float* lin2_w    = (const float*)d_in[16];
    const float* ln_ff_g   = (const float*)d_in[17];
    const float* ln_ff_b   = (const float*)d_in[18];
    const float* out_w     = (const float*)d_in[19];
    const float* out_b     = (const float*)d_in[20];
    float* out = (float*)d_out;

    float *X, *H2, *O;
    __half *X16, *Y16, *ATT16, *H16, *QW, *L1, *L2;
    cudaGetSymbolAddress((void**)&X,    g_x);
    cudaGetSymbolAddress((void**)&X16,  g_x16);
    cudaGetSymbolAddress((void**)&Y16,  g_y16);
    cudaGetSymbolAddress((void**)&ATT16,g_att16);
    cudaGetSymbolAddress((void**)&H16,  g_h16);
    cudaGetSymbolAddress((void**)&H2,   g_h2);
    cudaGetSymbolAddress((void**)&O,    g_o);
    cudaGetSymbolAddress((void**)&QW,   g_qkv_h);
    cudaGetSymbolAddress((void**)&L1,   g_l1_h);
    cudaGetSymbolAddress((void**)&L2,   g_l2_h);

    cudaFuncSetAttribute(gemm_fp16<false, false, true>,
                         cudaFuncAttributeMaxDynamicSharedMemorySize, GSMEM(false));
    cudaFuncSetAttribute(gemm_fp16<true, true, true>,
                         cudaFuncAttributeMaxDynamicSharedMemorySize, GSMEM(true));
    cudaFuncSetAttribute(gemm_fp16<true, true, false>,
                         cudaFuncAttributeMaxDynamicSharedMemorySize, GSMEM(true));

    conv_half_kernel<<<(LAYERS * 3 * DIM * DIM) / 1024, 256>>>(qkv,    QW);
    conv_half_kernel<<<(LAYERS * 2 * DIM * DIM) / 1024, 256>>>(lin1_w, L1);
    conv_half_kernel<<<(LAYERS * 2 * DIM * DIM) / 1024, 256>>>(lin2_w, L2);

    embed_ln_kernel<<<BT, 256>>>(fen, mv, rank_emb, file_emb, fen_emb, move_emb,
                                 ln_emb_g, ln_emb_b, X, X16);

    const size_t SLAB = (size_t)BT * DIM;
    for (int l = 0; l < LAYERS; l++) {
        // QKV -> Y16 (fp16), 3 slabs via grid.z
        gemm_fp16<false, false, true><<<dim3(8, BT / 128, 3), 256, GSMEM(false)>>>(
            X16, QW + (size_t)l * 3 * DIM * DIM, nullptr, Y16, BT, DIM, DIM);

        ln16_kernel<<<BT, 256>>>(Y16,        ln_q_g + l * DIM, ln_q_b + l * DIM);
        ln16_kernel<<<BT, 256>>>(Y16 + SLAB, ln_k_g + l * DIM, ln_k_b + l * DIM);

        scores_wmma<<<BATCH, 256>>>(Y16, Y16 + SLAB, ATT16);
        av_wmma<<<BATCH, 256>>>(ATT16, Y16 + 2 * SLAB, O);

        ln_res_kernel<<<BT, 256>>>(X, X16, O, ln_attn_g + l * DIM, ln_attn_b + l * DIM, 1);

        // FF: H16 = leaky(X @ lin1^T) fp16; H2 = leaky(H16 @ lin2^T) fp32
        gemm_fp16<true, true, true><<<dim3(16, BT / 128, 1), 256, GSMEM(true)>>>(
            X16, L1 + (size_t)l * 2 * DIM * DIM, nullptr, H16, BT, 2 * DIM, DIM);
        gemm_fp16<true, true, false><<<dim3(8, BT / 128, 1), 256, GSMEM(true)>>>(
            H16, L2 + (size_t)l * 2 * DIM * DIM, H2, nullptr, BT, DIM, 2 * DIM);

        ln_res_kernel<<<BT, 256>>>(X, X16, H2, ln_ff_g + l * DIM, ln_ff_b + l * DIM, 0);
    }

    head_kernel<<<BATCH, 256>>>(X, out_w, out_b, out);
}